// round 13
// baseline (speedup 1.0000x reference)
#include <cuda_runtime.h>
#include <cuda_fp16.h>
#include <math.h>
#include <stdint.h>

#define NC   4096
#define HCC  64
#define HM   128
#define CI   32
#define CC   64
#define BB   4
#define KS   4          // key-split factor

// ---------------- scratch ----------------
__device__ __half d_Qh[BB*NC*CI];
__device__ __half d_Kh[BB*NC*CI];
__device__ __half d_Vth[BB*CI*NC];     // transposed: [b][ci][n]
__device__ float  d_PO[KS*BB*NC*CI];   // unnormalized O partials
__device__ float  d_PD[KS*BB*NC];      // denominator partials
__device__ float  d_WOUT[BB*CC*NC];
__device__ float2 d_PARTF[128*CC];     // per-block BN partials
__device__ float2 d_STAT[CC];

__device__ __forceinline__ uint32_t pack2(float a, float b){
    __half2 h = __floats2half2_rn(a, b);
    return *(uint32_t*)&h;
}
__device__ __forceinline__ void mma16(float* d, const uint32_t* a, uint32_t b0, uint32_t b1){
    asm volatile("mma.sync.aligned.m16n8k16.row.col.f32.f16.f16.f32 "
        "{%0,%1,%2,%3}, {%4,%5,%6,%7}, {%8,%9}, {%0,%1,%2,%3};"
        : "+f"(d[0]),"+f"(d[1]),"+f"(d[2]),"+f"(d[3])
        : "r"(a[0]),"r"(a[1]),"r"(a[2]),"r"(a[3]), "r"(b0),"r"(b1));
}
__device__ __forceinline__ void cp16(void* smem_dst, const void* gsrc){
    uint32_t s = (uint32_t)__cvta_generic_to_shared(smem_dst);
    asm volatile("cp.async.cg.shared.global [%0], [%1], 16;" :: "r"(s), "l"(gsrc));
}
#define CP_COMMIT() asm volatile("cp.async.commit_group;" ::: "memory")
#define CP_WAIT1()  asm volatile("cp.async.wait_group 1;" ::: "memory")
#define CP_WAIT0()  asm volatile("cp.async.wait_group 0;" ::: "memory")

// ---------------- Kernel A: Q/K/V projections, 2-way channel split -------
// Q is pre-scaled by log2(e) so attention can use ex2 directly.
__global__ void __launch_bounds__(256) qkv_kernel(
        const float* __restrict__ crossf, const float* __restrict__ mainf,
        const float* __restrict__ gw, const float* __restrict__ gb,
        const float* __restrict__ tw, const float* __restrict__ tb,
        const float* __restrict__ pw, const float* __restrict__ pb) {
    __shared__ float sGW[CI*CC], sTW[CI*CC], sPW[CI*CC];
    __shared__ float sRed[128][CI+1];
    int tx = threadIdx.x, ty = threadIdx.y;
    int tid = ty*128 + tx;
    for (int i = tid; i < CI*CC; i += 256) { sGW[i]=gw[i]; sTW[i]=tw[i]; sPW[i]=pw[i]; }
    __syncthreads();

    int b = blockIdx.y;
    int n = blockIdx.x*128 + tx;

    float accQ[CI], accK[CI], accV[CI];
    #pragma unroll
    for (int ci=0; ci<CI; ci++) { accQ[ci]=0.f; accK[ci]=0.f; accV[ci]=0.f; }

    const float* cbase = crossf + (size_t)b*CC*NC + n;
    int i = n >> 6, j = n & 63;
    const float* mbase = mainf + (size_t)b*CC*HM*HM + (size_t)(2*i)*HM + 2*j;

    int c0 = ty*32;
    for (int c = c0; c < c0+32; c++) {
        float xv = cbase[(size_t)c*NC];
        const float* mr = mbase + (size_t)c*HM*HM;
        float2 m0 = *(const float2*)mr;
        float2 m1 = *(const float2*)(mr + HM);
        float pv = 0.25f*((m0.x + m0.y) + (m1.x + m1.y));
        #pragma unroll
        for (int ci=0; ci<CI; ci++) {
            accQ[ci] = fmaf(sGW[ci*CC+c], xv, accQ[ci]);
            accK[ci] = fmaf(sTW[ci*CC+c], xv, accK[ci]);
            accV[ci] = fmaf(sPW[ci*CC+c], pv, accV[ci]);
        }
    }

    __syncthreads();
    if (ty == 1) {
        #pragma unroll
        for (int ci=0; ci<CI; ci++) sRed[tx][ci] = accQ[ci];
    }
    __syncthreads();
    if (ty == 0) {
        #pragma unroll
        for (int ci=0; ci<CI; ci++) accQ[ci] += sRed[tx][ci] + gb[ci];
    }
    __syncthreads();
    if (ty == 1) {
        #pragma unroll
        for (int ci=0; ci<CI; ci++) sRed[tx][ci] = accK[ci];
    }
    __syncthreads();
    if (ty == 0) {
        #pragma unroll
        for (int ci=0; ci<CI; ci++) accK[ci] += sRed[tx][ci] + tb[ci];
    }
    __syncthreads();
    if (ty == 1) {
        #pragma unroll
        for (int ci=0; ci<CI; ci++) sRed[tx][ci] = accV[ci];
    }
    __syncthreads();
    if (ty == 0) {
        #pragma unroll
        for (int ci=0; ci<CI; ci++) accV[ci] += sRed[tx][ci] + pb[ci];

        const float L2E = 1.4426950408889634f;
        size_t ob = ((size_t)b*NC + n)*CI;
        uint32_t qp[16], kp[16];
        #pragma unroll
        for (int h = 0; h < 16; h++) {
            qp[h] = pack2(accQ[2*h]*L2E, accQ[2*h+1]*L2E);
            kp[h] = pack2(accK[2*h], accK[2*h+1]);
        }
        *(uint4*)&d_Qh[ob]     = make_uint4(qp[0], qp[1], qp[2], qp[3]);
        *(uint4*)&d_Qh[ob+8]   = make_uint4(qp[4], qp[5], qp[6], qp[7]);
        *(uint4*)&d_Qh[ob+16]  = make_uint4(qp[8], qp[9], qp[10],qp[11]);
        *(uint4*)&d_Qh[ob+24]  = make_uint4(qp[12],qp[13],qp[14],qp[15]);
        *(uint4*)&d_Kh[ob]     = make_uint4(kp[0], kp[1], kp[2], kp[3]);
        *(uint4*)&d_Kh[ob+8]   = make_uint4(kp[4], kp[5], kp[6], kp[7]);
        *(uint4*)&d_Kh[ob+16]  = make_uint4(kp[8], kp[9], kp[10],kp[11]);
        *(uint4*)&d_Kh[ob+24]  = make_uint4(kp[12],kp[13],kp[14],kp[15]);
        #pragma unroll
        for (int ci=0; ci<CI; ci++)
            d_Vth[((size_t)b*CI + ci)*NC + n] = __float2half_rn(accV[ci]);
    }
}

// ---------------- Kernel B: fp16 mma flash attention (key-split) ----------
// grid (32, BB, KS), 128 threads (4 warps). cp.async 2-stage K/V pipeline.
#define KSTRh 40    // halves per K row (80 B) -> conflict-free
#define VSTRh 136   // halves per Vt row (272 B) -> conflict-free

__global__ void __launch_bounds__(128, 1) attn_kernel() {
    __shared__ __half sK[2][128*KSTRh];
    __shared__ __half sVt[2][32*VSTRh];

    int tid = threadIdx.x, lane = tid & 31, w = tid >> 5;
    int gid = lane >> 2, tig = lane & 3;
    int b = blockIdx.y, qt = blockIdx.x, z = blockIdx.z;
    const uint32_t ONES = 0x3C003C00u;   // (1.0h, 1.0h)

    const __half* Kg = d_Kh + (size_t)b*NC*CI;
    const __half* Vg = d_Vth + (size_t)b*CI*NC;

    uint32_t qa[2][2][4];                // [mt][kci][reg]
    {
        const __half* Qb = d_Qh + ((size_t)(b*NC + qt*128 + w*32))*CI;
        #pragma unroll
        for (int mt=0; mt<2; mt++)
        #pragma unroll
        for (int kci=0; kci<2; kci++) {
            int r0 = (mt*16 + gid)*CI, r1 = r0 + 8*CI;
            int c0 = kci*16 + 2*tig, c1 = c0 + 8;
            qa[mt][kci][0] = *(const uint32_t*)&Qb[r0 + c0];
            qa[mt][kci][1] = *(const uint32_t*)&Qb[r1 + c0];
            qa[mt][kci][2] = *(const uint32_t*)&Qb[r0 + c1];
            qa[mt][kci][3] = *(const uint32_t*)&Qb[r1 + c1];
        }
    }

    float o[2][4][4];
    #pragma unroll
    for (int mt=0;mt<2;mt++)
    #pragma unroll
    for (int nc=0;nc<4;nc++)
    #pragma unroll
    for (int r=0;r<4;r++) o[mt][nc][r] = 0.f;
    float dacc[2][4];
    #pragma unroll
    for (int mt=0;mt<2;mt++)
    #pragma unroll
    for (int r=0;r<4;r++) dacc[mt][r] = 0.f;

    int t0 = z*8;
    // prologue: prefetch first tile into buffer 0
    {
        const __half* kb = Kg + (size_t)(t0*128 + tid)*CI;
        #pragma unroll
        for (int q=0; q<4; q++) cp16(&sK[0][tid*KSTRh + q*8], kb + q*8);
        #pragma unroll
        for (int i=0; i<4; i++) {
            int lin = i*128 + tid;
            int row = lin >> 4, q = lin & 15;
            cp16(&sVt[0][row*VSTRh + q*8], Vg + (size_t)row*NC + t0*128 + q*8);
        }
        CP_COMMIT();
    }

    int cur = 0;
    for (int t = t0; t < t0 + 8; t++) {
        __syncthreads();    // everyone done computing on the other buffer
        if (t + 1 < t0 + 8) {
            int nxt = cur ^ 1;
            const __half* kb = Kg + (size_t)((t+1)*128 + tid)*CI;
            #pragma unroll
            for (int q=0; q<4; q++) cp16(&sK[nxt][tid*KSTRh + q*8], kb + q*8);
            #pragma unroll
            for (int i=0; i<4; i++) {
                int lin = i*128 + tid;
                int row = lin >> 4, q = lin & 15;
                cp16(&sVt[nxt][row*VSTRh + q*8], Vg + (size_t)row*NC + (t+1)*128 + q*8);
            }
            CP_COMMIT();
            CP_WAIT1();
        } else {
            CP_WAIT0();
        }
        __syncthreads();    // current tile visible to all

        const __half* sKc = sK[cur];
        const __half* sVc = sVt[cur];

        #pragma unroll
        for (int ch = 0; ch < 8; ch++) {
            float s[2][2][4];
            #pragma unroll
            for (int mt=0;mt<2;mt++)
            #pragma unroll
            for (int ntk=0;ntk<2;ntk++)
            #pragma unroll
            for (int r=0;r<4;r++) s[mt][ntk][r] = 0.f;

            #pragma unroll
            for (int kci=0; kci<2; kci++) {
                #pragma unroll
                for (int ntk=0; ntk<2; ntk++) {
                    const __half* kr = &sKc[(ch*16 + ntk*8 + gid)*KSTRh + kci*16 + 2*tig];
                    uint32_t b0 = *(const uint32_t*)kr;
                    uint32_t b1 = *(const uint32_t*)(kr + 8);
                    mma16(s[0][ntk], qa[0][kci], b0, b1);
                    mma16(s[1][ntk], qa[1][kci], b0, b1);
                }
            }

            uint32_t pa[2][4];
            #pragma unroll
            for (int mt=0; mt<2; mt++) {
                #pragma unroll
                for (int ntk=0; ntk<2; ntk++) {
                    uint32_t h0 = pack2(s[mt][ntk][0], s[mt][ntk][1]);
                    uint32_t h1 = pack2(s[mt][ntk][2], s[mt][ntk][3]);
                    asm("ex2.approx.f16x2 %0, %0;" : "+r"(h0));
                    asm("ex2.approx.f16x2 %0, %0;" : "+r"(h1));
                    pa[mt][2*ntk]   = h0;
                    pa[mt][2*ntk+1] = h1;
                }
                mma16(dacc[mt], pa[mt], ONES, ONES);   // exact fp32 row sums
            }

            #pragma unroll
            for (int nc=0; nc<4; nc++) {
                const __half* vr = &sVc[(nc*8 + gid)*VSTRh + ch*16 + 2*tig];
                uint32_t vb0 = *(const uint32_t*)vr;
                uint32_t vb1 = *(const uint32_t*)(vr + 8);
                mma16(o[0][nc], pa[0], vb0, vb1);
                mma16(o[1][nc], pa[1], vb0, vb1);
            }
        }
        cur ^= 1;
    }

    size_t zb = (size_t)(z*BB + b);
    #pragma unroll
    for (int mt=0; mt<2; mt++) {
        int row0 = qt*128 + w*32 + mt*16 + gid;
        if (tig == 0) {
            d_PD[zb*NC + row0]     = dacc[mt][0];
            d_PD[zb*NC + row0 + 8] = dacc[mt][2];
        }
        #pragma unroll
        for (int nc=0; nc<4; nc++) {
            int col = nc*8 + 2*tig;
            *(float2*)&d_PO[(zb*NC + row0)*CI + col] =
                make_float2(o[mt][nc][0], o[mt][nc][1]);
            *(float2*)&d_PO[(zb*NC + row0 + 8)*CI + col] =
                make_float2(o[mt][nc][2], o[mt][nc][3]);
        }
    }
}

// ---------------- Kernel C: fused combine + W conv + BN partials ----------
__global__ void __launch_bounds__(128) cw_kernel(const float* __restrict__ ww,
                                                 const float* __restrict__ wb) {
    __shared__ float sW[CI][CC];
    __shared__ float sSum[CC][5], sSq[CC][5];     // [co][warp] padded
    int t = threadIdx.x, lane = t & 31, wp = t >> 5;
    for (int i = t; i < CI*CC; i += 128) {
        int ci = i & 31, co = i >> 5;
        sW[ci][co] = ww[i];
    }
    __syncthreads();

    int idx = blockIdx.x*128 + t;      // b*NC + n
    int b = idx >> 12, n = idx & 4095;

    float den = 0.f;
    #pragma unroll
    for (int z=0; z<KS; z++)
        den += d_PD[((size_t)(z*BB + b))*NC + n];
    float inv = 1.f / den;

    float a[CI];
    #pragma unroll
    for (int c4 = 0; c4 < 8; c4++) {
        float4 acc = make_float4(0.f,0.f,0.f,0.f);
        #pragma unroll
        for (int z=0; z<KS; z++) {
            float4 p = *(const float4*)&d_PO[(((size_t)(z*BB + b))*NC + n)*CI + c4*4];
            acc.x += p.x; acc.y += p.y; acc.z += p.z; acc.w += p.w;
        }
        a[c4*4+0] = acc.x*inv; a[c4*4+1] = acc.y*inv;
        a[c4*4+2] = acc.z*inv; a[c4*4+3] = acc.w*inv;
    }

    float* wout = d_WOUT + (size_t)b*CC*NC + n;
    #pragma unroll
    for (int co = 0; co < CC; co++) {
        float s = wb[co];
        #pragma unroll
        for (int ci=0; ci<CI; ci++) s = fmaf(sW[ci][co], a[ci], s);
        wout[(size_t)co*NC] = s;
        // fused BN partial: warp-reduce sum & sumsq
        float ss = s, qq = s*s;
        #pragma unroll
        for (int off=16; off>0; off>>=1) {
            ss += __shfl_down_sync(0xFFFFFFFFu, ss, off);
            qq += __shfl_down_sync(0xFFFFFFFFu, qq, off);
        }
        if (lane == 0) { sSum[co][wp] = ss; sSq[co][wp] = qq; }
    }
    __syncthreads();
    if (t < CC) {
        float S = (sSum[t][0] + sSum[t][1]) + (sSum[t][2] + sSum[t][3]);
        float Q = (sSq[t][0]  + sSq[t][1])  + (sSq[t][2]  + sSq[t][3]);
        d_PARTF[blockIdx.x*CC + t] = make_float2(S, Q);
    }
}

// ---------------- Kernel C2: finalize BN affine ---------------------------
__global__ void bnfin_kernel(const float* __restrict__ gamma, const float* __restrict__ beta) {
    int co = threadIdx.x;
    double s = 0.0, q = 0.0;
    for (int i = 0; i < 128; i++) {
        float2 p = d_PARTF[i*CC + co];
        s += (double)p.x; q += (double)p.y;
    }
    const double N = (double)(BB*NC);
    double mean = s / N;
    double var  = q / N - mean*mean;
    float rsv = rsqrtf((float)var + 1e-5f);
    float a = gamma[co] * rsv;
    d_STAT[co] = make_float2(a, beta[co] - (float)mean * a);
}

// ---------------- Kernel C3: BN + bilinear upsample + residual ---------
__device__ __forceinline__ void lin_coords(int i, float scale, int n_in, int& i0, int& i1, float& f) {
    float src = ((float)i + 0.5f) * scale - 0.5f;
    src = fminf(fmaxf(src, 0.f), (float)(n_in-1));
    i0 = (int)floorf(src);
    i1 = min(i0 + 1, n_in - 1);
    f  = src - (float)i0;
}

__global__ void out_kernel(const float* __restrict__ mainf, float* __restrict__ out) {
    int idx = blockIdx.x*256 + threadIdx.x;
    int w  = idx & 127;
    int h  = (idx >> 7) & 127;
    int bc = idx >> 14;
    int co = bc & 63;

    int h0,h1,w0,w1; float fh,fw;
    lin_coords(h, 0.5f, HCC, h0, h1, fh);
    lin_coords(w, 0.5f, HCC, w0, w1, fw);

    const float* wp = &d_WOUT[(size_t)bc*NC];
    float v00 = wp[h0*HCC + w0], v01 = wp[h0*HCC + w1];
    float v10 = wp[h1*HCC + w0], v11 = wp[h1*HCC + w1];
    float v0 = v00*(1.f-fw) + v01*fw;
    float v1 = v10*(1.f-fw) + v11*fw;
    float v  = v0*(1.f-fh) + v1*fh;

    float2 st = d_STAT[co];
    out[idx] = fmaf(st.x, v, st.y) + mainf[idx];
}

// ---------------- launch ---------------------------------------------------
extern "C" void kernel_launch(void* const* d_in, const int* in_sizes, int n_in,
                              void* d_out, int out_size) {
    const float* mainf = (const float*)d_in[0];
    const float* crossf= (const float*)d_in[1];
    const float* gw    = (const float*)d_in[2];
    const float* gb    = (const float*)d_in[3];
    const float* tw    = (const float*)d_in[4];
    const float* tb    = (const float*)d_in[5];
    const float* pw    = (const float*)d_in[6];
    const float* pb    = (const float*)d_in[7];
    const float* ww    = (const float*)d_in[8];
    const float* wb    = (const float*)d_in[9];
    const float* bng   = (const float*)d_in[10];
    const float* bnb   = (const float*)d_in[11];
    float* out = (float*)d_out;

    qkv_kernel<<<dim3(32, BB), dim3(128, 2)>>>(crossf, mainf, gw, gb, tw, tb, pw, pb);
    attn_kernel<<<dim3(32, BB, KS), 128>>>();
    cw_kernel<<<128, 128>>>(ww, wb);
    bnfin_kernel<<<1, 64>>>(bng, bnb);
    out_kernel<<<(BB*CC*HM*HM)/256, 256>>>(mainf, out);
}

// round 14
// speedup vs baseline: 1.9985x; 1.9985x over previous
#include <cuda_runtime.h>
#include <cuda_fp16.h>
#include <math.h>
#include <stdint.h>

#define NC   4096
#define HCC  64
#define HM   128
#define CI   32
#define CC   64
#define BB   4
#define KS   4          // key-split factor

// ---------------- scratch ----------------
__device__ __half d_Qh[BB*NC*CI];
__device__ __half d_Kh[BB*NC*CI];
__device__ __half d_Vth[BB*CI*NC];     // transposed: [b][ci][n]
__device__ float  d_PO[KS*BB*NC*CI];   // unnormalized O partials
__device__ float  d_PD[KS*BB*NC];      // denominator partials
__device__ float  d_WOUT[BB*CC*NC];
__device__ double2 d_PART[CC*16];
__device__ float2 d_STAT[CC];

__device__ __forceinline__ uint32_t pack2(float a, float b){
    __half2 h = __floats2half2_rn(a, b);
    return *(uint32_t*)&h;
}
__device__ __forceinline__ void mma16(float* d, const uint32_t* a, uint32_t b0, uint32_t b1){
    asm volatile("mma.sync.aligned.m16n8k16.row.col.f32.f16.f16.f32 "
        "{%0,%1,%2,%3}, {%4,%5,%6,%7}, {%8,%9}, {%0,%1,%2,%3};"
        : "+f"(d[0]),"+f"(d[1]),"+f"(d[2]),"+f"(d[3])
        : "r"(a[0]),"r"(a[1]),"r"(a[2]),"r"(a[3]), "r"(b0),"r"(b1));
}
__device__ __forceinline__ void cp16(void* smem_dst, const void* gsrc){
    uint32_t s = (uint32_t)__cvta_generic_to_shared(smem_dst);
    asm volatile("cp.async.cg.shared.global [%0], [%1], 16;" :: "r"(s), "l"(gsrc));
}
#define CP_COMMIT() asm volatile("cp.async.commit_group;" ::: "memory")
#define CP_WAIT1()  asm volatile("cp.async.wait_group 1;" ::: "memory")
#define CP_WAIT0()  asm volatile("cp.async.wait_group 0;" ::: "memory")

// ---------------- Kernel A: Q/K/V projections, 2-way channel split -------
__global__ void __launch_bounds__(256) qkv_kernel(
        const float* __restrict__ crossf, const float* __restrict__ mainf,
        const float* __restrict__ gw, const float* __restrict__ gb,
        const float* __restrict__ tw, const float* __restrict__ tb,
        const float* __restrict__ pw, const float* __restrict__ pb) {
    __shared__ float sGW[CI*CC], sTW[CI*CC], sPW[CI*CC];
    __shared__ float sRed[128][CI+1];
    int tx = threadIdx.x, ty = threadIdx.y;
    int tid = ty*128 + tx;
    for (int i = tid; i < CI*CC; i += 256) { sGW[i]=gw[i]; sTW[i]=tw[i]; sPW[i]=pw[i]; }
    __syncthreads();

    int b = blockIdx.y;
    int n = blockIdx.x*128 + tx;

    float accQ[CI], accK[CI], accV[CI];
    #pragma unroll
    for (int ci=0; ci<CI; ci++) { accQ[ci]=0.f; accK[ci]=0.f; accV[ci]=0.f; }

    const float* cbase = crossf + (size_t)b*CC*NC + n;
    int i = n >> 6, j = n & 63;
    const float* mbase = mainf + (size_t)b*CC*HM*HM + (size_t)(2*i)*HM + 2*j;

    int c0 = ty*32;
    for (int c = c0; c < c0+32; c++) {
        float xv = cbase[(size_t)c*NC];
        const float* mr = mbase + (size_t)c*HM*HM;
        float2 m0 = *(const float2*)mr;
        float2 m1 = *(const float2*)(mr + HM);
        float pv = 0.25f*((m0.x + m0.y) + (m1.x + m1.y));
        #pragma unroll
        for (int ci=0; ci<CI; ci++) {
            accQ[ci] = fmaf(sGW[ci*CC+c], xv, accQ[ci]);
            accK[ci] = fmaf(sTW[ci*CC+c], xv, accK[ci]);
            accV[ci] = fmaf(sPW[ci*CC+c], pv, accV[ci]);
        }
    }

    __syncthreads();
    if (ty == 1) {
        #pragma unroll
        for (int ci=0; ci<CI; ci++) sRed[tx][ci] = accQ[ci];
    }
    __syncthreads();
    if (ty == 0) {
        #pragma unroll
        for (int ci=0; ci<CI; ci++) accQ[ci] += sRed[tx][ci] + gb[ci];
    }
    __syncthreads();
    if (ty == 1) {
        #pragma unroll
        for (int ci=0; ci<CI; ci++) sRed[tx][ci] = accK[ci];
    }
    __syncthreads();
    if (ty == 0) {
        #pragma unroll
        for (int ci=0; ci<CI; ci++) accK[ci] += sRed[tx][ci] + tb[ci];
    }
    __syncthreads();
    if (ty == 1) {
        #pragma unroll
        for (int ci=0; ci<CI; ci++) sRed[tx][ci] = accV[ci];
    }
    __syncthreads();
    if (ty == 0) {
        #pragma unroll
        for (int ci=0; ci<CI; ci++) accV[ci] += sRed[tx][ci] + pb[ci];

        const float L2E = 1.4426950408889634f;
        size_t ob = ((size_t)b*NC + n)*CI;
        uint32_t qp[16], kp[16];
        #pragma unroll
        for (int h = 0; h < 16; h++) {
            qp[h] = pack2(accQ[2*h]*L2E, accQ[2*h+1]*L2E);
            kp[h] = pack2(accK[2*h], accK[2*h+1]);
        }
        *(uint4*)&d_Qh[ob]     = make_uint4(qp[0], qp[1], qp[2], qp[3]);
        *(uint4*)&d_Qh[ob+8]   = make_uint4(qp[4], qp[5], qp[6], qp[7]);
        *(uint4*)&d_Qh[ob+16]  = make_uint4(qp[8], qp[9], qp[10],qp[11]);
        *(uint4*)&d_Qh[ob+24]  = make_uint4(qp[12],qp[13],qp[14],qp[15]);
        *(uint4*)&d_Kh[ob]     = make_uint4(kp[0], kp[1], kp[2], kp[3]);
        *(uint4*)&d_Kh[ob+8]   = make_uint4(kp[4], kp[5], kp[6], kp[7]);
        *(uint4*)&d_Kh[ob+16]  = make_uint4(kp[8], kp[9], kp[10],kp[11]);
        *(uint4*)&d_Kh[ob+24]  = make_uint4(kp[12],kp[13],kp[14],kp[15]);
        #pragma unroll
        for (int ci=0; ci<CI; ci++)
            d_Vth[((size_t)b*CI + ci)*NC + n] = __float2half_rn(accV[ci]);
    }
}

// ---------------- Kernel B: fp16 mma flash attention (cp.async 2-stage) ---
#define KSTRh 40    // halves per K row (80 B) -> conflict-free
#define VSTRh 136   // halves per Vt row (272 B) -> conflict-free

__global__ void __launch_bounds__(128, 1) attn_kernel() {
    __shared__ __half sK[2][128*KSTRh];
    __shared__ __half sVt[2][32*VSTRh];

    int tid = threadIdx.x, lane = tid & 31, w = tid >> 5;
    int gid = lane >> 2, tig = lane & 3;
    int b = blockIdx.y, qt = blockIdx.x, z = blockIdx.z;
    const uint32_t ONES = 0x3C003C00u;   // (1.0h, 1.0h)

    const __half* Kg = d_Kh + (size_t)b*NC*CI;
    const __half* Vg = d_Vth + (size_t)b*CI*NC;

    uint32_t qa[2][2][4];                // [mt][kci][reg]
    {
        const __half* Qb = d_Qh + ((size_t)(b*NC + qt*128 + w*32))*CI;
        #pragma unroll
        for (int mt=0; mt<2; mt++)
        #pragma unroll
        for (int kci=0; kci<2; kci++) {
            int r0 = (mt*16 + gid)*CI, r1 = r0 + 8*CI;
            int c0 = kci*16 + 2*tig, c1 = c0 + 8;
            qa[mt][kci][0] = *(const uint32_t*)&Qb[r0 + c0];
            qa[mt][kci][1] = *(const uint32_t*)&Qb[r1 + c0];
            qa[mt][kci][2] = *(const uint32_t*)&Qb[r0 + c1];
            qa[mt][kci][3] = *(const uint32_t*)&Qb[r1 + c1];
        }
    }

    float o[2][4][4];
    #pragma unroll
    for (int mt=0;mt<2;mt++)
    #pragma unroll
    for (int nc=0;nc<4;nc++)
    #pragma unroll
    for (int r=0;r<4;r++) o[mt][nc][r] = 0.f;
    float dacc[2][4];
    #pragma unroll
    for (int mt=0;mt<2;mt++)
    #pragma unroll
    for (int r=0;r<4;r++) dacc[mt][r] = 0.f;

    int t0 = z*8;
    {
        const __half* kb = Kg + (size_t)(t0*128 + tid)*CI;
        #pragma unroll
        for (int q=0; q<4; q++) cp16(&sK[0][tid*KSTRh + q*8], kb + q*8);
        #pragma unroll
        for (int i=0; i<4; i++) {
            int lin = i*128 + tid;
            int row = lin >> 4, q = lin & 15;
            cp16(&sVt[0][row*VSTRh + q*8], Vg + (size_t)row*NC + t0*128 + q*8);
        }
        CP_COMMIT();
    }

    int cur = 0;
    for (int t = t0; t < t0 + 8; t++) {
        __syncthreads();
        if (t + 1 < t0 + 8) {
            int nxt = cur ^ 1;
            const __half* kb = Kg + (size_t)((t+1)*128 + tid)*CI;
            #pragma unroll
            for (int q=0; q<4; q++) cp16(&sK[nxt][tid*KSTRh + q*8], kb + q*8);
            #pragma unroll
            for (int i=0; i<4; i++) {
                int lin = i*128 + tid;
                int row = lin >> 4, q = lin & 15;
                cp16(&sVt[nxt][row*VSTRh + q*8], Vg + (size_t)row*NC + (t+1)*128 + q*8);
            }
            CP_COMMIT();
            CP_WAIT1();
        } else {
            CP_WAIT0();
        }
        __syncthreads();

        const __half* sKc = sK[cur];
        const __half* sVc = sVt[cur];

        #pragma unroll
        for (int ch = 0; ch < 8; ch++) {
            float s[2][2][4];
            #pragma unroll
            for (int mt=0;mt<2;mt++)
            #pragma unroll
            for (int ntk=0;ntk<2;ntk++)
            #pragma unroll
            for (int r=0;r<4;r++) s[mt][ntk][r] = 0.f;

            #pragma unroll
            for (int kci=0; kci<2; kci++) {
                #pragma unroll
                for (int ntk=0; ntk<2; ntk++) {
                    const __half* kr = &sKc[(ch*16 + ntk*8 + gid)*KSTRh + kci*16 + 2*tig];
                    uint32_t b0 = *(const uint32_t*)kr;
                    uint32_t b1 = *(const uint32_t*)(kr + 8);
                    mma16(s[0][ntk], qa[0][kci], b0, b1);
                    mma16(s[1][ntk], qa[1][kci], b0, b1);
                }
            }

            uint32_t pa[2][4];
            #pragma unroll
            for (int mt=0; mt<2; mt++) {
                #pragma unroll
                for (int ntk=0; ntk<2; ntk++) {
                    uint32_t h0 = pack2(s[mt][ntk][0], s[mt][ntk][1]);
                    uint32_t h1 = pack2(s[mt][ntk][2], s[mt][ntk][3]);
                    asm("ex2.approx.f16x2 %0, %0;" : "+r"(h0));
                    asm("ex2.approx.f16x2 %0, %0;" : "+r"(h1));
                    pa[mt][2*ntk]   = h0;
                    pa[mt][2*ntk+1] = h1;
                }
                mma16(dacc[mt], pa[mt], ONES, ONES);
            }

            #pragma unroll
            for (int nc=0; nc<4; nc++) {
                const __half* vr = &sVc[(nc*8 + gid)*VSTRh + ch*16 + 2*tig];
                uint32_t vb0 = *(const uint32_t*)vr;
                uint32_t vb1 = *(const uint32_t*)(vr + 8);
                mma16(o[0][nc], pa[0], vb0, vb1);
                mma16(o[1][nc], pa[1], vb0, vb1);
            }
        }
        cur ^= 1;
    }

    size_t zb = (size_t)(z*BB + b);
    #pragma unroll
    for (int mt=0; mt<2; mt++) {
        int row0 = qt*128 + w*32 + mt*16 + gid;
        if (tig == 0) {
            d_PD[zb*NC + row0]     = dacc[mt][0];
            d_PD[zb*NC + row0 + 8] = dacc[mt][2];
        }
        #pragma unroll
        for (int nc=0; nc<4; nc++) {
            int col = nc*8 + 2*tig;
            *(float2*)&d_PO[(zb*NC + row0)*CI + col] =
                make_float2(o[mt][nc][0], o[mt][nc][1]);
            *(float2*)&d_PO[(zb*NC + row0 + 8)*CI + col] =
                make_float2(o[mt][nc][2], o[mt][nc][3]);
        }
    }
}

// ---------------- Kernel C: fused combine + W conv (round-12 version) -----
__global__ void __launch_bounds__(128) cw_kernel(const float* __restrict__ ww,
                                                 const float* __restrict__ wb) {
    __shared__ float sW[CI][CC];
    int t = threadIdx.x;
    for (int i = t; i < CI*CC; i += 128) {
        int ci = i & 31, co = i >> 5;
        sW[ci][co] = ww[i];
    }
    __syncthreads();

    int idx = blockIdx.x*128 + t;      // b*NC + n
    int b = idx >> 12, n = idx & 4095;

    float den = 0.f;
    #pragma unroll
    for (int z=0; z<KS; z++)
        den += d_PD[((size_t)(z*BB + b))*NC + n];
    float inv = 1.f / den;

    float a[CI];
    #pragma unroll
    for (int c4 = 0; c4 < 8; c4++) {
        float4 acc = make_float4(0.f,0.f,0.f,0.f);
        #pragma unroll
        for (int z=0; z<KS; z++) {
            float4 p = *(const float4*)&d_PO[(((size_t)(z*BB + b))*NC + n)*CI + c4*4];
            acc.x += p.x; acc.y += p.y; acc.z += p.z; acc.w += p.w;
        }
        a[c4*4+0] = acc.x*inv; a[c4*4+1] = acc.y*inv;
        a[c4*4+2] = acc.z*inv; a[c4*4+3] = acc.w*inv;
    }

    float* wout = d_WOUT + (size_t)b*CC*NC + n;
    #pragma unroll
    for (int co = 0; co < CC; co++) {
        float s = wb[co];
        #pragma unroll
        for (int ci=0; ci<CI; ci++) s = fmaf(sW[ci][co], a[ci], s);
        wout[(size_t)co*NC] = s;
    }
}

// ---------------- Kernel C2a: BN partial stats (shuffle reduce) -----------
__global__ void bnpart_kernel() {
    __shared__ float sS[4], sQ[4];
    int co = blockIdx.x, sl = blockIdx.y, t = threadIdx.x;
    int lane = t & 31, wp = t >> 5;
    int b = sl >> 2, q4 = sl & 3;
    const float4* base = (const float4*)(d_WOUT + ((size_t)b*CC + co)*NC + q4*1024);
    float4 v0 = base[t], v1 = base[t + 128];
    float s = (v0.x + v0.y) + (v0.z + v0.w) + (v1.x + v1.y) + (v1.z + v1.w);
    float q = (v0.x*v0.x + v0.y*v0.y) + (v0.z*v0.z + v0.w*v0.w)
            + (v1.x*v1.x + v1.y*v1.y) + (v1.z*v1.z + v1.w*v1.w);
    #pragma unroll
    for (int off=16; off>0; off>>=1) {
        s += __shfl_down_sync(0xFFFFFFFFu, s, off);
        q += __shfl_down_sync(0xFFFFFFFFu, q, off);
    }
    if (lane == 0) { sS[wp] = s; sQ[wp] = q; }
    __syncthreads();
    if (t == 0) {
        float S = (sS[0] + sS[1]) + (sS[2] + sS[3]);
        float Q = (sQ[0] + sQ[1]) + (sQ[2] + sQ[3]);
        d_PART[co*16 + sl] = make_double2((double)S, (double)Q);
    }
}

// ---------------- Kernel C2b: finalize BN affine --------------------------
__global__ void bnfin_kernel(const float* __restrict__ gamma, const float* __restrict__ beta) {
    int co = threadIdx.x;
    double s = 0.0, q = 0.0;
    #pragma unroll
    for (int i = 0; i < 16; i++) {
        double2 p = d_PART[co*16 + i];
        s += p.x; q += p.y;
    }
    const double N = (double)(BB*NC);
    double mean = s / N;
    double var  = q / N - mean*mean;
    float rsv = rsqrtf((float)var + 1e-5f);
    float a = gamma[co] * rsv;
    d_STAT[co] = make_float2(a, beta[co] - (float)mean * a);
}

// ---------------- Kernel C3: BN + bilinear upsample + residual ---------
__device__ __forceinline__ void lin_coords(int i, float scale, int n_in, int& i0, int& i1, float& f) {
    float src = ((float)i + 0.5f) * scale - 0.5f;
    src = fminf(fmaxf(src, 0.f), (float)(n_in-1));
    i0 = (int)floorf(src);
    i1 = min(i0 + 1, n_in - 1);
    f  = src - (float)i0;
}

__global__ void out_kernel(const float* __restrict__ mainf, float* __restrict__ out) {
    int idx = blockIdx.x*256 + threadIdx.x;
    int w  = idx & 127;
    int h  = (idx >> 7) & 127;
    int bc = idx >> 14;
    int co = bc & 63;

    int h0,h1,w0,w1; float fh,fw;
    lin_coords(h, 0.5f, HCC, h0, h1, fh);
    lin_coords(w, 0.5f, HCC, w0, w1, fw);

    const float* wp = &d_WOUT[(size_t)bc*NC];
    float v00 = wp[h0*HCC + w0], v01 = wp[h0*HCC + w1];
    float v10 = wp[h1*HCC + w0], v11 = wp[h1*HCC + w1];
    float v0 = v00*(1.f-fw) + v01*fw;
    float v1 = v10*(1.f-fw) + v11*fw;
    float v  = v0*(1.f-fh) + v1*fh;

    float2 st = d_STAT[co];
    out[idx] = fmaf(st.x, v, st.y) + mainf[idx];
}

// ---------------- launch ---------------------------------------------------
extern "C" void kernel_launch(void* const* d_in, const int* in_sizes, int n_in,
                              void* d_out, int out_size) {
    const float* mainf = (const float*)d_in[0];
    const float* crossf= (const float*)d_in[1];
    const float* gw    = (const float*)d_in[2];
    const float* gb    = (const float*)d_in[3];
    const float* tw    = (const float*)d_in[4];
    const float* tb    = (const float*)d_in[5];
    const float* pw    = (const float*)d_in[6];
    const float* pb    = (const float*)d_in[7];
    const float* ww    = (const float*)d_in[8];
    const float* wb    = (const float*)d_in[9];
    const float* bng   = (const float*)d_in[10];
    const float* bnb   = (const float*)d_in[11];
    float* out = (float*)d_out;

    qkv_kernel<<<dim3(32, BB), dim3(128, 2)>>>(crossf, mainf, gw, gb, tw, tb, pw, pb);
    attn_kernel<<<dim3(32, BB, KS), 128>>>();
    cw_kernel<<<128, 128>>>(ww, wb);
    bnpart_kernel<<<dim3(CC, 16), 128>>>();
    bnfin_kernel<<<1, 64>>>(bng, bnb);
    out_kernel<<<(BB*CC*HM*HM)/256, 256>>>(mainf, out);
}

// round 16
// speedup vs baseline: 2.0418x; 1.0217x over previous
#include <cuda_runtime.h>
#include <cuda_fp16.h>
#include <math.h>
#include <stdint.h>

#define NC   4096
#define HCC  64
#define HM   128
#define CI   32
#define CC   64
#define BB   4
#define KS   8          // key-split factor

// ---------------- scratch ----------------
__device__ __half d_Qh[BB*NC*CI];
__device__ __half d_Kh[BB*NC*CI];
__device__ __half d_Vth[BB*CI*NC];     // transposed: [b][ci][n]
__device__ float  d_PO[KS*BB*NC*CI];   // unnormalized O partials (16 MB)
__device__ float  d_PD[KS*BB*NC];      // denominator partials
__device__ float  d_WOUT[BB*CC*NC];
__device__ double2 d_PART[CC*2];
__device__ float2 d_STAT[CC];

__device__ __forceinline__ uint32_t pack2(float a, float b){
    __half2 h = __floats2half2_rn(a, b);
    return *(uint32_t*)&h;
}
__device__ __forceinline__ float2 h2f2(uint32_t u){
    return __half22float2(*(__half2*)&u);
}
__device__ __forceinline__ void mma16(float* d, const uint32_t* a, uint32_t b0, uint32_t b1){
    asm volatile("mma.sync.aligned.m16n8k16.row.col.f32.f16.f16.f32 "
        "{%0,%1,%2,%3}, {%4,%5,%6,%7}, {%8,%9}, {%0,%1,%2,%3};"
        : "+f"(d[0]),"+f"(d[1]),"+f"(d[2]),"+f"(d[3])
        : "r"(a[0]),"r"(a[1]),"r"(a[2]),"r"(a[3]), "r"(b0),"r"(b1));
}
__device__ __forceinline__ void cp16(void* smem_dst, const void* gsrc){
    uint32_t s = (uint32_t)__cvta_generic_to_shared(smem_dst);
    asm volatile("cp.async.cg.shared.global [%0], [%1], 16;" :: "r"(s), "l"(gsrc));
}
#define CP_COMMIT() asm volatile("cp.async.commit_group;" ::: "memory")
#define CP_WAIT1()  asm volatile("cp.async.wait_group 1;" ::: "memory")
#define CP_WAIT0()  asm volatile("cp.async.wait_group 0;" ::: "memory")

// ---------------- Kernel A: Q/K/V projections, 2-way channel split -------
__global__ void __launch_bounds__(256) qkv_kernel(
        const float* __restrict__ crossf, const float* __restrict__ mainf,
        const float* __restrict__ gw, const float* __restrict__ gb,
        const float* __restrict__ tw, const float* __restrict__ tb,
        const float* __restrict__ pw, const float* __restrict__ pb) {
    __shared__ float sGW[CI*CC], sTW[CI*CC], sPW[CI*CC];
    __shared__ float sRed[128][CI+1];
    int tx = threadIdx.x, ty = threadIdx.y;
    int tid = ty*128 + tx;
    for (int i = tid; i < CI*CC; i += 256) { sGW[i]=gw[i]; sTW[i]=tw[i]; sPW[i]=pw[i]; }
    __syncthreads();

    int b = blockIdx.y;
    int n = blockIdx.x*128 + tx;

    float accQ[CI], accK[CI], accV[CI];
    #pragma unroll
    for (int ci=0; ci<CI; ci++) { accQ[ci]=0.f; accK[ci]=0.f; accV[ci]=0.f; }

    const float* cbase = crossf + (size_t)b*CC*NC + n;
    int i = n >> 6, j = n & 63;
    const float* mbase = mainf + (size_t)b*CC*HM*HM + (size_t)(2*i)*HM + 2*j;

    int c0 = ty*32;
    for (int c = c0; c < c0+32; c++) {
        float xv = cbase[(size_t)c*NC];
        const float* mr = mbase + (size_t)c*HM*HM;
        float2 m0 = *(const float2*)mr;
        float2 m1 = *(const float2*)(mr + HM);
        float pv = 0.25f*((m0.x + m0.y) + (m1.x + m1.y));
        #pragma unroll
        for (int ci=0; ci<CI; ci++) {
            accQ[ci] = fmaf(sGW[ci*CC+c], xv, accQ[ci]);
            accK[ci] = fmaf(sTW[ci*CC+c], xv, accK[ci]);
            accV[ci] = fmaf(sPW[ci*CC+c], pv, accV[ci]);
        }
    }

    __syncthreads();
    if (ty == 1) {
        #pragma unroll
        for (int ci=0; ci<CI; ci++) sRed[tx][ci] = accQ[ci];
    }
    __syncthreads();
    if (ty == 0) {
        #pragma unroll
        for (int ci=0; ci<CI; ci++) accQ[ci] += sRed[tx][ci] + gb[ci];
    }
    __syncthreads();
    if (ty == 1) {
        #pragma unroll
        for (int ci=0; ci<CI; ci++) sRed[tx][ci] = accK[ci];
    }
    __syncthreads();
    if (ty == 0) {
        #pragma unroll
        for (int ci=0; ci<CI; ci++) accK[ci] += sRed[tx][ci] + tb[ci];
    }
    __syncthreads();
    if (ty == 1) {
        #pragma unroll
        for (int ci=0; ci<CI; ci++) sRed[tx][ci] = accV[ci];
    }
    __syncthreads();
    if (ty == 0) {
        #pragma unroll
        for (int ci=0; ci<CI; ci++) accV[ci] += sRed[tx][ci] + pb[ci];

        const float L2E = 1.4426950408889634f;
        size_t ob = ((size_t)b*NC + n)*CI;
        uint32_t qp[16], kp[16];
        #pragma unroll
        for (int h = 0; h < 16; h++) {
            qp[h] = pack2(accQ[2*h]*L2E, accQ[2*h+1]*L2E);
            kp[h] = pack2(accK[2*h], accK[2*h+1]);
        }
        *(uint4*)&d_Qh[ob]     = make_uint4(qp[0], qp[1], qp[2], qp[3]);
        *(uint4*)&d_Qh[ob+8]   = make_uint4(qp[4], qp[5], qp[6], qp[7]);
        *(uint4*)&d_Qh[ob+16]  = make_uint4(qp[8], qp[9], qp[10],qp[11]);
        *(uint4*)&d_Qh[ob+24]  = make_uint4(qp[12],qp[13],qp[14],qp[15]);
        *(uint4*)&d_Kh[ob]     = make_uint4(kp[0], kp[1], kp[2], kp[3]);
        *(uint4*)&d_Kh[ob+8]   = make_uint4(kp[4], kp[5], kp[6], kp[7]);
        *(uint4*)&d_Kh[ob+16]  = make_uint4(kp[8], kp[9], kp[10],kp[11]);
        *(uint4*)&d_Kh[ob+24]  = make_uint4(kp[12],kp[13],kp[14],kp[15]);
        #pragma unroll
        for (int ci=0; ci<CI; ci++)
            d_Vth[((size_t)b*CI + ci)*NC + n] = __float2half_rn(accV[ci]);
    }
}

// ---------------- Kernel B: fp16 mma flash attention (key-split 8) --------
#define KSTRh 40    // halves per K row (80 B) -> conflict-free
#define VSTRh 136   // halves per Vt row (272 B) -> conflict-free

__global__ void __launch_bounds__(128, 1) attn_kernel() {
    __shared__ __half sK[2][128*KSTRh];
    __shared__ __half sVt[2][32*VSTRh];

    int tid = threadIdx.x, lane = tid & 31, w = tid >> 5;
    int gid = lane >> 2, tig = lane & 3;
    int b = blockIdx.y, qt = blockIdx.x, z = blockIdx.z;

    const __half* Kg = d_Kh + (size_t)b*NC*CI;
    const __half* Vg = d_Vth + (size_t)b*CI*NC;

    uint32_t qa[2][2][4];                // [mt][kci][reg]
    {
        const __half* Qb = d_Qh + ((size_t)(b*NC + qt*128 + w*32))*CI;
        #pragma unroll
        for (int mt=0; mt<2; mt++)
        #pragma unroll
        for (int kci=0; kci<2; kci++) {
            int r0 = (mt*16 + gid)*CI, r1 = r0 + 8*CI;
            int c0 = kci*16 + 2*tig, c1 = c0 + 8;
            qa[mt][kci][0] = *(const uint32_t*)&Qb[r0 + c0];
            qa[mt][kci][1] = *(const uint32_t*)&Qb[r1 + c0];
            qa[mt][kci][2] = *(const uint32_t*)&Qb[r0 + c1];
            qa[mt][kci][3] = *(const uint32_t*)&Qb[r1 + c1];
        }
    }

    float o[2][4][4];
    #pragma unroll
    for (int mt=0;mt<2;mt++)
    #pragma unroll
    for (int nc=0;nc<4;nc++)
    #pragma unroll
    for (int r=0;r<4;r++) o[mt][nc][r] = 0.f;
    float den[2][2] = {{0.f,0.f},{0.f,0.f}};

    int t0 = z*4;
    {
        const __half* kb = Kg + (size_t)(t0*128 + tid)*CI;
        #pragma unroll
        for (int q=0; q<4; q++) cp16(&sK[0][tid*KSTRh + q*8], kb + q*8);
        #pragma unroll
        for (int i=0; i<4; i++) {
            int lin = i*128 + tid;
            int row = lin >> 4, q = lin & 15;
            cp16(&sVt[0][row*VSTRh + q*8], Vg + (size_t)row*NC + t0*128 + q*8);
        }
        CP_COMMIT();
    }

    int cur = 0;
    for (int t = t0; t < t0 + 4; t++) {
        __syncthreads();
        if (t + 1 < t0 + 4) {
            int nxt = cur ^ 1;
            const __half* kb = Kg + (size_t)((t+1)*128 + tid)*CI;
            #pragma unroll
            for (int q=0; q<4; q++) cp16(&sK[nxt][tid*KSTRh + q*8], kb + q*8);
            #pragma unroll
            for (int i=0; i<4; i++) {
                int lin = i*128 + tid;
                int row = lin >> 4, q = lin & 15;
                cp16(&sVt[nxt][row*VSTRh + q*8], Vg + (size_t)row*NC + (t+1)*128 + q*8);
            }
            CP_COMMIT();
            CP_WAIT1();
        } else {
            CP_WAIT0();
        }
        __syncthreads();

        const __half* sKc = sK[cur];
        const __half* sVc = sVt[cur];

        #pragma unroll
        for (int ch = 0; ch < 8; ch++) {
            float s[2][2][4];
            #pragma unroll
            for (int mt=0;mt<2;mt++)
            #pragma unroll
            for (int ntk=0;ntk<2;ntk++)
            #pragma unroll
            for (int r=0;r<4;r++) s[mt][ntk][r] = 0.f;

            #pragma unroll
            for (int kci=0; kci<2; kci++) {
                #pragma unroll
                for (int ntk=0; ntk<2; ntk++) {
                    const __half* kr = &sKc[(ch*16 + ntk*8 + gid)*KSTRh + kci*16 + 2*tig];
                    uint32_t b0 = *(const uint32_t*)kr;
                    uint32_t b1 = *(const uint32_t*)(kr + 8);
                    mma16(s[0][ntk], qa[0][kci], b0, b1);
                    mma16(s[1][ntk], qa[1][kci], b0, b1);
                }
            }

            // ---- p = 2^s via half2 MUFU; den summed on fma pipe (fp32) ----
            uint32_t pa[2][4];
            #pragma unroll
            for (int mt=0; mt<2; mt++) {
                #pragma unroll
                for (int ntk=0; ntk<2; ntk++) {
                    uint32_t h0 = pack2(s[mt][ntk][0], s[mt][ntk][1]);
                    uint32_t h1 = pack2(s[mt][ntk][2], s[mt][ntk][3]);
                    asm("ex2.approx.f16x2 %0, %0;" : "+r"(h0));
                    asm("ex2.approx.f16x2 %0, %0;" : "+r"(h1));
                    pa[mt][2*ntk]   = h0;   // rows gid (cols pair)
                    pa[mt][2*ntk+1] = h1;   // rows gid+8
                }
                float2 f0 = h2f2(pa[mt][0]), f1 = h2f2(pa[mt][1]);
                float2 f2 = h2f2(pa[mt][2]), f3 = h2f2(pa[mt][3]);
                den[mt][0] += (f0.x + f0.y) + (f2.x + f2.y);
                den[mt][1] += (f1.x + f1.y) + (f3.x + f3.y);
            }

            #pragma unroll
            for (int nc=0; nc<4; nc++) {
                const __half* vr = &sVc[(nc*8 + gid)*VSTRh + ch*16 + 2*tig];
                uint32_t vb0 = *(const uint32_t*)vr;
                uint32_t vb1 = *(const uint32_t*)(vr + 8);
                mma16(o[0][nc], pa[0], vb0, vb1);
                mma16(o[1][nc], pa[1], vb0, vb1);
            }
        }
        cur ^= 1;
    }

    // ---- reduce denominators across quads ----
    #pragma unroll
    for (int mt=0; mt<2; mt++)
    #pragma unroll
    for (int h=0; h<2; h++) {
        float d = den[mt][h];
        d += __shfl_xor_sync(0xFFFFFFFFu, d, 1);
        d += __shfl_xor_sync(0xFFFFFFFFu, d, 2);
        den[mt][h] = d;
    }

    size_t zb = (size_t)(z*BB + b);
    #pragma unroll
    for (int mt=0; mt<2; mt++) {
        int row0 = qt*128 + w*32 + mt*16 + gid;
        if (tig == 0) {
            d_PD[zb*NC + row0]     = den[mt][0];
            d_PD[zb*NC + row0 + 8] = den[mt][1];
        }
        #pragma unroll
        for (int nc=0; nc<4; nc++) {
            int col = nc*8 + 2*tig;
            *(float2*)&d_PO[(zb*NC + row0)*CI + col] =
                make_float2(o[mt][nc][0], o[mt][nc][1]);
            *(float2*)&d_PO[(zb*NC + row0 + 8)*CI + col] =
                make_float2(o[mt][nc][2], o[mt][nc][3]);
        }
    }
}

// ---------------- Kernel C: fused combine + W conv ------------------------
__global__ void __launch_bounds__(128) cw_kernel(const float* __restrict__ ww,
                                                 const float* __restrict__ wb) {
    __shared__ float sW[CI][CC];
    int t = threadIdx.x;
    for (int i = t; i < CI*CC; i += 128) {
        int ci = i & 31, co = i >> 5;
        sW[ci][co] = ww[i];
    }
    __syncthreads();

    int idx = blockIdx.x*128 + t;      // b*NC + n
    int b = idx >> 12, n = idx & 4095;

    float den = 0.f;
    #pragma unroll
    for (int z=0; z<KS; z++)
        den += d_PD[((size_t)(z*BB + b))*NC + n];
    float inv = 1.f / den;

    float a[CI];
    #pragma unroll
    for (int c4 = 0; c4 < 8; c4++) {
        float4 acc = make_float4(0.f,0.f,0.f,0.f);
        #pragma unroll
        for (int z=0; z<KS; z++) {
            float4 p = *(const float4*)&d_PO[(((size_t)(z*BB + b))*NC + n)*CI + c4*4];
            acc.x += p.x; acc.y += p.y; acc.z += p.z; acc.w += p.w;
        }
        a[c4*4+0] = acc.x*inv; a[c4*4+1] = acc.y*inv;
        a[c4*4+2] = acc.z*inv; a[c4*4+3] = acc.w*inv;
    }

    float* wout = d_WOUT + (size_t)b*CC*NC + n;
    #pragma unroll
    for (int co = 0; co < CC; co++) {
        float s = wb[co];
        #pragma unroll
        for (int ci=0; ci<CI; ci++) s = fmaf(sW[ci][co], a[ci], s);
        wout[(size_t)co*NC] = s;
    }
}

// ---------------- Kernel C2a: BN partial stats (MLP 8) --------------------
__global__ void __launch_bounds__(256) bnpart_kernel() {
    __shared__ float sS[8], sQ[8];
    int co = blockIdx.x, sl = blockIdx.y, t = threadIdx.x;
    int lane = t & 31, wp = t >> 5;
    const float4* p0 = (const float4*)(d_WOUT + ((size_t)(2*sl)*CC + co)*NC);
    const float4* p1 = (const float4*)(d_WOUT + ((size_t)(2*sl+1)*CC + co)*NC);
    float4 v[8];
    #pragma unroll
    for (int i=0;i<4;i++) { v[i] = p0[t + 256*i]; v[4+i] = p1[t + 256*i]; }
    float s = 0.f, q = 0.f;
    #pragma unroll
    for (int i=0;i<8;i++) {
        s += (v[i].x + v[i].y) + (v[i].z + v[i].w);
        q += (v[i].x*v[i].x + v[i].y*v[i].y) + (v[i].z*v[i].z + v[i].w*v[i].w);
    }
    #pragma unroll
    for (int off=16; off>0; off>>=1) {
        s += __shfl_down_sync(0xFFFFFFFFu, s, off);
        q += __shfl_down_sync(0xFFFFFFFFu, q, off);
    }
    if (lane == 0) { sS[wp] = s; sQ[wp] = q; }
    __syncthreads();
    if (t == 0) {
        float S = ((sS[0]+sS[1])+(sS[2]+sS[3])) + ((sS[4]+sS[5])+(sS[6]+sS[7]));
        float Q = ((sQ[0]+sQ[1])+(sQ[2]+sQ[3])) + ((sQ[4]+sQ[5])+(sQ[6]+sQ[7]));
        d_PART[co*2 + sl] = make_double2((double)S, (double)Q);
    }
}

// ---------------- Kernel C2b: finalize BN affine --------------------------
__global__ void bnfin_kernel(const float* __restrict__ gamma, const float* __restrict__ beta) {
    int co = threadIdx.x;
    double2 pa = d_PART[co*2], pb2 = d_PART[co*2+1];
    double s = pa.x + pb2.x, q = pa.y + pb2.y;
    const double N = (double)(BB*NC);
    double mean = s / N;
    double var  = q / N - mean*mean;
    float rsv = rsqrtf((float)var + 1e-5f);
    float a = gamma[co] * rsv;
    d_STAT[co] = make_float2(a, beta[co] - (float)mean * a);
}

// ---------------- Kernel C3: BN + bilinear upsample + residual (x4) -------
__device__ __forceinline__ void lin_coords(int i, float scale, int n_in, int& i0, int& i1, float& f) {
    float src = ((float)i + 0.5f) * scale - 0.5f;
    src = fminf(fmaxf(src, 0.f), (float)(n_in-1));
    i0 = (int)floorf(src);
    i1 = min(i0 + 1, n_in - 1);
    f  = src - (float)i0;
}

__global__ void __launch_bounds__(256) out_kernel(const float* __restrict__ mainf,
                                                  float* __restrict__ out) {
    int idx4 = blockIdx.x*256 + threadIdx.x;   // float4 index
    int jw = idx4 & 31;
    int h  = (idx4 >> 5) & 127;
    int bc = idx4 >> 12;
    int co = bc & 63;

    int h0,h1; float fh;
    lin_coords(h, 0.5f, HCC, h0, h1, fh);

    int c0 = max(2*jw - 1, 0), c1 = 2*jw, c2 = 2*jw + 1, c3 = min(2*jw + 2, 63);
    const float* wp = &d_WOUT[(size_t)bc*NC];
    const float* r0 = wp + h0*HCC;
    const float* r1 = wp + h1*HCC;
    float a0=r0[c0], a1=r0[c1], a2=r0[c2], a3=r0[c3];
    float e0=r1[c0], e1=r1[c1], e2=r1[c2], e3=r1[c3];

    // top/bottom row lerps for the 4 outputs
    float t0 = a0 + 0.75f*(a1 - a0);
    float t1 = a1 + 0.25f*(a2 - a1);
    float t2 = a1 + 0.75f*(a2 - a1);
    float t3 = a2 + 0.25f*(a3 - a2);
    float u0 = e0 + 0.75f*(e1 - e0);
    float u1 = e1 + 0.25f*(e2 - e1);
    float u2 = e1 + 0.75f*(e2 - e1);
    float u3 = e2 + 0.25f*(e3 - e2);

    float v0 = t0 + fh*(u0 - t0);
    float v1 = t1 + fh*(u1 - t1);
    float v2 = t2 + fh*(u2 - t2);
    float v3 = t3 + fh*(u3 - t3);

    float2 st = d_STAT[co];
    float4 m = *(const float4*)&mainf[(size_t)idx4*4];
    float4 r;
    r.x = fmaf(st.x, v0, st.y) + m.x;
    r.y = fmaf(st.x, v1, st.y) + m.y;
    r.z = fmaf(st.x, v2, st.y) + m.z;
    r.w = fmaf(st.x, v3, st.y) + m.w;
    *(float4*)&out[(size_t)idx4*4] = r;
}

// ---------------- launch ---------------------------------------------------
extern "C" void kernel_launch(void* const* d_in, const int* in_sizes, int n_in,
                              void* d_out, int out_size) {
    const float* mainf = (const float*)d_in[0];
    const float* crossf= (const float*)d_in[1];
    const float* gw    = (const float*)d_in[2];
    const float* gb    = (const float*)d_in[3];
    const float* tw    = (const float*)d_in[4];
    const float* tb    = (const float*)d_in[5];
    const float* pw    = (const float*)d_in[6];
    const float* pb    = (const float*)d_in[7];
    const float* ww    = (const float*)d_in[8];
    const float* wb    = (const float*)d_in[9];
    const float* bng   = (const float*)d_in[10];
    const float* bnb   = (const float*)d_in[11];
    float* out = (float*)d_out;

    qkv_kernel<<<dim3(32, BB), dim3(128, 2)>>>(crossf, mainf, gw, gb, tw, tb, pw, pb);
    attn_kernel<<<dim3(32, BB, KS), 128>>>();
    cw_kernel<<<128, 128>>>(ww, wb);
    bnpart_kernel<<<dim3(CC, 2), 256>>>();
    bnfin_kernel<<<1, 64>>>(bng, bnb);
    out_kernel<<<(BB*CC*HM*HM)/1024, 256>>>(mainf, out);
}

// round 17
// speedup vs baseline: 2.0538x; 1.0058x over previous
#include <cuda_runtime.h>
#include <cuda_fp16.h>
#include <math.h>
#include <stdint.h>

#define NC   4096
#define HCC  64
#define HM   128
#define CI   32
#define CC   64
#define BB   4
#define KS   4          // key-split factor

// ---------------- scratch ----------------
__device__ __half d_Qh[BB*NC*CI];
__device__ __half d_Kh[BB*NC*CI];
__device__ __half d_Vth[BB*CI*NC];     // transposed: [b][ci][n]
__device__ float  d_PO[KS*BB*NC*CI];   // unnormalized O partials (8 MB)
__device__ float  d_PD[KS*BB*NC];      // denominator partials
__device__ float  d_WOUT[BB*CC*NC];
__device__ double2 d_PART[CC*2];
__device__ float2 d_STAT[CC];

__device__ __forceinline__ uint32_t pack2(float a, float b){
    __half2 h = __floats2half2_rn(a, b);
    return *(uint32_t*)&h;
}
__device__ __forceinline__ float2 h2f2(uint32_t u){
    return __half22float2(*(__half2*)&u);
}
__device__ __forceinline__ void mma16(float* d, const uint32_t* a, uint32_t b0, uint32_t b1){
    asm volatile("mma.sync.aligned.m16n8k16.row.col.f32.f16.f16.f32 "
        "{%0,%1,%2,%3}, {%4,%5,%6,%7}, {%8,%9}, {%0,%1,%2,%3};"
        : "+f"(d[0]),"+f"(d[1]),"+f"(d[2]),"+f"(d[3])
        : "r"(a[0]),"r"(a[1]),"r"(a[2]),"r"(a[3]), "r"(b0),"r"(b1));
}
__device__ __forceinline__ void ldsm4(uint32_t* r, const void* p){
    uint32_t a = (uint32_t)__cvta_generic_to_shared(p);
    asm volatile("ldmatrix.sync.aligned.m8n8.x4.shared.b16 {%0,%1,%2,%3}, [%4];"
        : "=r"(r[0]),"=r"(r[1]),"=r"(r[2]),"=r"(r[3]) : "r"(a));
}
__device__ __forceinline__ void cp16(void* smem_dst, const void* gsrc){
    uint32_t s = (uint32_t)__cvta_generic_to_shared(smem_dst);
    asm volatile("cp.async.cg.shared.global [%0], [%1], 16;" :: "r"(s), "l"(gsrc));
}
#define CP_COMMIT() asm volatile("cp.async.commit_group;" ::: "memory")
#define CP_WAIT1()  asm volatile("cp.async.wait_group 1;" ::: "memory")
#define CP_WAIT0()  asm volatile("cp.async.wait_group 0;" ::: "memory")

// ---------------- Kernel A: Q/K/V projections, 2-way channel split -------
__global__ void __launch_bounds__(256) qkv_kernel(
        const float* __restrict__ crossf, const float* __restrict__ mainf,
        const float* __restrict__ gw, const float* __restrict__ gb,
        const float* __restrict__ tw, const float* __restrict__ tb,
        const float* __restrict__ pw, const float* __restrict__ pb) {
    __shared__ float sGW[CI*CC], sTW[CI*CC], sPW[CI*CC];
    __shared__ float sRed[128][CI+1];
    int tx = threadIdx.x, ty = threadIdx.y;
    int tid = ty*128 + tx;
    for (int i = tid; i < CI*CC; i += 256) { sGW[i]=gw[i]; sTW[i]=tw[i]; sPW[i]=pw[i]; }
    __syncthreads();

    int b = blockIdx.y;
    int n = blockIdx.x*128 + tx;

    float accQ[CI], accK[CI], accV[CI];
    #pragma unroll
    for (int ci=0; ci<CI; ci++) { accQ[ci]=0.f; accK[ci]=0.f; accV[ci]=0.f; }

    const float* cbase = crossf + (size_t)b*CC*NC + n;
    int i = n >> 6, j = n & 63;
    const float* mbase = mainf + (size_t)b*CC*HM*HM + (size_t)(2*i)*HM + 2*j;

    int c0 = ty*32;
    for (int c = c0; c < c0+32; c++) {
        float xv = cbase[(size_t)c*NC];
        const float* mr = mbase + (size_t)c*HM*HM;
        float2 m0 = *(const float2*)mr;
        float2 m1 = *(const float2*)(mr + HM);
        float pv = 0.25f*((m0.x + m0.y) + (m1.x + m1.y));
        #pragma unroll
        for (int ci=0; ci<CI; ci++) {
            accQ[ci] = fmaf(sGW[ci*CC+c], xv, accQ[ci]);
            accK[ci] = fmaf(sTW[ci*CC+c], xv, accK[ci]);
            accV[ci] = fmaf(sPW[ci*CC+c], pv, accV[ci]);
        }
    }

    __syncthreads();
    if (ty == 1) {
        #pragma unroll
        for (int ci=0; ci<CI; ci++) sRed[tx][ci] = accQ[ci];
    }
    __syncthreads();
    if (ty == 0) {
        #pragma unroll
        for (int ci=0; ci<CI; ci++) accQ[ci] += sRed[tx][ci] + gb[ci];
    }
    __syncthreads();
    if (ty == 1) {
        #pragma unroll
        for (int ci=0; ci<CI; ci++) sRed[tx][ci] = accK[ci];
    }
    __syncthreads();
    if (ty == 0) {
        #pragma unroll
        for (int ci=0; ci<CI; ci++) accK[ci] += sRed[tx][ci] + tb[ci];
    }
    __syncthreads();
    if (ty == 1) {
        #pragma unroll
        for (int ci=0; ci<CI; ci++) sRed[tx][ci] = accV[ci];
    }
    __syncthreads();
    if (ty == 0) {
        #pragma unroll
        for (int ci=0; ci<CI; ci++) accV[ci] += sRed[tx][ci] + pb[ci];

        const float L2E = 1.4426950408889634f;
        size_t ob = ((size_t)b*NC + n)*CI;
        uint32_t qp[16], kp[16];
        #pragma unroll
        for (int h = 0; h < 16; h++) {
            qp[h] = pack2(accQ[2*h]*L2E, accQ[2*h+1]*L2E);
            kp[h] = pack2(accK[2*h], accK[2*h+1]);
        }
        *(uint4*)&d_Qh[ob]     = make_uint4(qp[0], qp[1], qp[2], qp[3]);
        *(uint4*)&d_Qh[ob+8]   = make_uint4(qp[4], qp[5], qp[6], qp[7]);
        *(uint4*)&d_Qh[ob+16]  = make_uint4(qp[8], qp[9], qp[10],qp[11]);
        *(uint4*)&d_Qh[ob+24]  = make_uint4(qp[12],qp[13],qp[14],qp[15]);
        *(uint4*)&d_Kh[ob]     = make_uint4(kp[0], kp[1], kp[2], kp[3]);
        *(uint4*)&d_Kh[ob+8]   = make_uint4(kp[4], kp[5], kp[6], kp[7]);
        *(uint4*)&d_Kh[ob+16]  = make_uint4(kp[8], kp[9], kp[10],kp[11]);
        *(uint4*)&d_Kh[ob+24]  = make_uint4(kp[12],kp[13],kp[14],kp[15]);
        #pragma unroll
        for (int ci=0; ci<CI; ci++)
            d_Vth[((size_t)b*CI + ci)*NC + n] = __float2half_rn(accV[ci]);
    }
}

// ---------------- Kernel B: fp16 mma flash attention (ldmatrix) ----------
#define KSTRh 40    // halves per K row (80 B) -> ldsm conflict-free
#define VSTRh 136   // halves per Vt row (272 B) -> ldsm conflict-free

__global__ void __launch_bounds__(128, 1) attn_kernel() {
    __shared__ __half sK[2][128*KSTRh];
    __shared__ __half sVt[2][32*VSTRh];

    int tid = threadIdx.x, lane = tid & 31, w = tid >> 5;
    int gid = lane >> 2, tig = lane & 3;
    int b = blockIdx.y, qt = blockIdx.x, z = blockIdx.z;

    const __half* Kg = d_Kh + (size_t)b*NC*CI;
    const __half* Vg = d_Vth + (size_t)b*CI*NC;

    uint32_t qa[2][2][4];                // [mt][kci][reg]
    {
        const __half* Qb = d_Qh + ((size_t)(b*NC + qt*128 + w*32))*CI;
        #pragma unroll
        for (int mt=0; mt<2; mt++)
        #pragma unroll
        for (int kci=0; kci<2; kci++) {
            int r0 = (mt*16 + gid)*CI, r1 = r0 + 8*CI;
            int c0 = kci*16 + 2*tig, c1 = c0 + 8;
            qa[mt][kci][0] = *(const uint32_t*)&Qb[r0 + c0];
            qa[mt][kci][1] = *(const uint32_t*)&Qb[r1 + c0];
            qa[mt][kci][2] = *(const uint32_t*)&Qb[r0 + c1];
            qa[mt][kci][3] = *(const uint32_t*)&Qb[r1 + c1];
        }
    }

    float o[2][4][4];
    #pragma unroll
    for (int mt=0;mt<2;mt++)
    #pragma unroll
    for (int nc=0;nc<4;nc++)
    #pragma unroll
    for (int r=0;r<4;r++) o[mt][nc][r] = 0.f;
    float den[2][2] = {{0.f,0.f},{0.f,0.f}};

    // ldmatrix per-lane base offsets (matrix m = lane>>3, row r = lane&7)
    int lm = lane >> 3, lr = lane & 7;
    // K: matrices (ntk, half): row = ch*16 + (m>>1)*8 + r, col = kci*16 + (m&1)*8
    int koff_base = ((lm >> 1)*8 + lr)*KSTRh + (lm & 1)*8;
    // V: matrices (nc, half): row = ncbase*8 + (m>>1)*8 + r, col = ch*16 + (m&1)*8
    int voff_base = ((lm >> 1)*8 + lr)*VSTRh + (lm & 1)*8;

    int t0 = z*8;
    {
        const __half* kb = Kg + (size_t)(t0*128 + tid)*CI;
        #pragma unroll
        for (int q=0; q<4; q++) cp16(&sK[0][tid*KSTRh + q*8], kb + q*8);
        #pragma unroll
        for (int i=0; i<4; i++) {
            int lin = i*128 + tid;
            int row = lin >> 4, q = lin & 15;
            cp16(&sVt[0][row*VSTRh + q*8], Vg + (size_t)row*NC + t0*128 + q*8);
        }
        CP_COMMIT();
    }

    int cur = 0;
    for (int t = t0; t < t0 + 8; t++) {
        __syncthreads();
        if (t + 1 < t0 + 8) {
            int nxt = cur ^ 1;
            const __half* kb = Kg + (size_t)((t+1)*128 + tid)*CI;
            #pragma unroll
            for (int q=0; q<4; q++) cp16(&sK[nxt][tid*KSTRh + q*8], kb + q*8);
            #pragma unroll
            for (int i=0; i<4; i++) {
                int lin = i*128 + tid;
                int row = lin >> 4, q = lin & 15;
                cp16(&sVt[nxt][row*VSTRh + q*8], Vg + (size_t)row*NC + (t+1)*128 + q*8);
            }
            CP_COMMIT();
            CP_WAIT1();
        } else {
            CP_WAIT0();
        }
        __syncthreads();

        const __half* sKc = sK[cur];
        const __half* sVc = sVt[cur];

        #pragma unroll
        for (int ch = 0; ch < 8; ch++) {
            // ---- B fragments via ldmatrix ----
            uint32_t kb0[4], kb1[4];                 // [kci][(ntk0 b0, ntk0 b1, ntk1 b0, ntk1 b1)]
            const __half* kaddr = &sKc[ch*16*KSTRh + koff_base];
            ldsm4(kb0, kaddr);
            ldsm4(kb1, kaddr + 16);

            float s[2][2][4];
            #pragma unroll
            for (int mt=0;mt<2;mt++)
            #pragma unroll
            for (int ntk=0;ntk<2;ntk++)
            #pragma unroll
            for (int r=0;r<4;r++) s[mt][ntk][r] = 0.f;

            #pragma unroll
            for (int mt=0; mt<2; mt++) {
                mma16(s[mt][0], qa[mt][0], kb0[0], kb0[1]);
                mma16(s[mt][1], qa[mt][0], kb0[2], kb0[3]);
                mma16(s[mt][0], qa[mt][1], kb1[0], kb1[1]);
                mma16(s[mt][1], qa[mt][1], kb1[2], kb1[3]);
            }

            // ---- p = 2^s via half2 MUFU; den summed on fma pipe ----
            uint32_t pa[2][4];
            #pragma unroll
            for (int mt=0; mt<2; mt++) {
                #pragma unroll
                for (int ntk=0; ntk<2; ntk++) {
                    uint32_t h0 = pack2(s[mt][ntk][0], s[mt][ntk][1]);
                    uint32_t h1 = pack2(s[mt][ntk][2], s[mt][ntk][3]);
                    asm("ex2.approx.f16x2 %0, %0;" : "+r"(h0));
                    asm("ex2.approx.f16x2 %0, %0;" : "+r"(h1));
                    pa[mt][2*ntk]   = h0;   // rows gid
                    pa[mt][2*ntk+1] = h1;   // rows gid+8
                }
                float2 f0 = h2f2(pa[mt][0]), f1 = h2f2(pa[mt][1]);
                float2 f2 = h2f2(pa[mt][2]), f3 = h2f2(pa[mt][3]);
                den[mt][0] += (f0.x + f0.y) + (f2.x + f2.y);
                den[mt][1] += (f1.x + f1.y) + (f3.x + f3.y);
            }

            // ---- O += P V (V fragments via ldmatrix) ----
            uint32_t vb0[4], vb1[4];                 // (nc0 b0, nc0 b1, nc1 b0, nc1 b1), (nc2.., nc3..)
            const __half* vaddr = &sVc[voff_base + ch*16];
            ldsm4(vb0, vaddr);
            ldsm4(vb1, vaddr + 16*VSTRh);

            #pragma unroll
            for (int mt=0; mt<2; mt++) {
                mma16(o[mt][0], pa[mt], vb0[0], vb0[1]);
                mma16(o[mt][1], pa[mt], vb0[2], vb0[3]);
                mma16(o[mt][2], pa[mt], vb1[0], vb1[1]);
                mma16(o[mt][3], pa[mt], vb1[2], vb1[3]);
            }
        }
        cur ^= 1;
    }

    // ---- reduce denominators across quads ----
    #pragma unroll
    for (int mt=0; mt<2; mt++)
    #pragma unroll
    for (int h=0; h<2; h++) {
        float d = den[mt][h];
        d += __shfl_xor_sync(0xFFFFFFFFu, d, 1);
        d += __shfl_xor_sync(0xFFFFFFFFu, d, 2);
        den[mt][h] = d;
    }

    size_t zb = (size_t)(z*BB + b);
    #pragma unroll
    for (int mt=0; mt<2; mt++) {
        int row0 = qt*128 + w*32 + mt*16 + gid;
        if (tig == 0) {
            d_PD[zb*NC + row0]     = den[mt][0];
            d_PD[zb*NC + row0 + 8] = den[mt][1];
        }
        #pragma unroll
        for (int nc=0; nc<4; nc++) {
            int col = nc*8 + 2*tig;
            *(float2*)&d_PO[(zb*NC + row0)*CI + col] =
                make_float2(o[mt][nc][0], o[mt][nc][1]);
            *(float2*)&d_PO[(zb*NC + row0 + 8)*CI + col] =
                make_float2(o[mt][nc][2], o[mt][nc][3]);
        }
    }
}

// ---------------- Kernel C: fused combine + W conv ------------------------
__global__ void __launch_bounds__(128) cw_kernel(const float* __restrict__ ww,
                                                 const float* __restrict__ wb) {
    __shared__ float sW[CI][CC];
    int t = threadIdx.x;
    for (int i = t; i < CI*CC; i += 128) {
        int ci = i & 31, co = i >> 5;
        sW[ci][co] = ww[i];
    }
    __syncthreads();

    int idx = blockIdx.x*128 + t;      // b*NC + n
    int b = idx >> 12, n = idx & 4095;

    float den = 0.f;
    #pragma unroll
    for (int z=0; z<KS; z++)
        den += d_PD[((size_t)(z*BB + b))*NC + n];
    float inv = 1.f / den;

    float a[CI];
    #pragma unroll
    for (int c4 = 0; c4 < 8; c4++) {
        float4 acc = make_float4(0.f,0.f,0.f,0.f);
        #pragma unroll
        for (int z=0; z<KS; z++) {
            float4 p = *(const float4*)&d_PO[(((size_t)(z*BB + b))*NC + n)*CI + c4*4];
            acc.x += p.x; acc.y += p.y; acc.z += p.z; acc.w += p.w;
        }
        a[c4*4+0] = acc.x*inv; a[c4*4+1] = acc.y*inv;
        a[c4*4+2] = acc.z*inv; a[c4*4+3] = acc.w*inv;
    }

    float* wout = d_WOUT + (size_t)b*CC*NC + n;
    #pragma unroll
    for (int co = 0; co < CC; co++) {
        float s = wb[co];
        #pragma unroll
        for (int ci=0; ci<CI; ci++) s = fmaf(sW[ci][co], a[ci], s);
        wout[(size_t)co*NC] = s;
    }
}

// ---------------- Kernel C2a: BN partial stats (MLP 8) --------------------
__global__ void __launch_bounds__(256) bnpart_kernel() {
    __shared__ float sS[8], sQ[8];
    int co = blockIdx.x, sl = blockIdx.y, t = threadIdx.x;
    int lane = t & 31, wp = t >> 5;
    const float4* p0 = (const float4*)(d_WOUT + ((size_t)(2*sl)*CC + co)*NC);
    const float4* p1 = (const float4*)(d_WOUT + ((size_t)(2*sl+1)*CC + co)*NC);
    float4 v[8];
    #pragma unroll
    for (int i=0;i<4;i++) { v[i] = p0[t + 256*i]; v[4+i] = p1[t + 256*i]; }
    float s = 0.f, q = 0.f;
    #pragma unroll
    for (int i=0;i<8;i++) {
        s += (v[i].x + v[i].y) + (v[i].z + v[i].w);
        q += (v[i].x*v[i].x + v[i].y*v[i].y) + (v[i].z*v[i].z + v[i].w*v[i].w);
    }
    #pragma unroll
    for (int off=16; off>0; off>>=1) {
        s += __shfl_down_sync(0xFFFFFFFFu, s, off);
        q += __shfl_down_sync(0xFFFFFFFFu, q, off);
    }
    if (lane == 0) { sS[wp] = s; sQ[wp] = q; }
    __syncthreads();
    if (t == 0) {
        float S = ((sS[0]+sS[1])+(sS[2]+sS[3])) + ((sS[4]+sS[5])+(sS[6]+sS[7]));
        float Q = ((sQ[0]+sQ[1])+(sQ[2]+sQ[3])) + ((sQ[4]+sQ[5])+(sQ[6]+sQ[7]));
        d_PART[co*2 + sl] = make_double2((double)S, (double)Q);
    }
}

// ---------------- Kernel C2b: finalize BN affine --------------------------
__global__ void bnfin_kernel(const float* __restrict__ gamma, const float* __restrict__ beta) {
    int co = threadIdx.x;
    double2 pa = d_PART[co*2], pb2 = d_PART[co*2+1];
    double s = pa.x + pb2.x, q = pa.y + pb2.y;
    const double N = (double)(BB*NC);
    double mean = s / N;
    double var  = q / N - mean*mean;
    float rsv = rsqrtf((float)var + 1e-5f);
    float a = gamma[co] * rsv;
    d_STAT[co] = make_float2(a, beta[co] - (float)mean * a);
}

// ---------------- Kernel C3: BN + bilinear upsample + residual (x4) -------
__device__ __forceinline__ void lin_coords(int i, float scale, int n_in, int& i0, int& i1, float& f) {
    float src = ((float)i + 0.5f) * scale - 0.5f;
    src = fminf(fmaxf(src, 0.f), (float)(n_in-1));
    i0 = (int)floorf(src);
    i1 = min(i0 + 1, n_in - 1);
    f  = src - (float)i0;
}

__global__ void __launch_bounds__(256) out_kernel(const float* __restrict__ mainf,
                                                  float* __restrict__ out) {
    int idx4 = blockIdx.x*256 + threadIdx.x;   // float4 index
    int jw = idx4 & 31;
    int h  = (idx4 >> 5) & 127;
    int bc = idx4 >> 12;
    int co = bc & 63;

    int h0,h1; float fh;
    lin_coords(h, 0.5f, HCC, h0, h1, fh);

    int c0 = max(2*jw - 1, 0), c1 = 2*jw, c2 = 2*jw + 1, c3 = min(2*jw + 2, 63);
    const float* wp = &d_WOUT[(size_t)bc*NC];
    const float* r0 = wp + h0*HCC;
    const float* r1 = wp + h1*HCC;
    float a0=r0[c0], a1=r0[c1], a2=r0[c2], a3=r0[c3];
    float e0=r1[c0], e1=r1[c1], e2=r1[c2], e3=r1[c3];

    float t0 = a0 + 0.75f*(a1 - a0);
    float t1 = a1 + 0.25f*(a2 - a1);
    float t2 = a1 + 0.75f*(a2 - a1);
    float t3 = a2 + 0.25f*(a3 - a2);
    float u0 = e0 + 0.75f*(e1 - e0);
    float u1 = e1 + 0.25f*(e2 - e1);
    float u2 = e1 + 0.75f*(e2 - e1);
    float u3 = e2 + 0.25f*(e3 - e2);

    float v0 = t0 + fh*(u0 - t0);
    float v1 = t1 + fh*(u1 - t1);
    float v2 = t2 + fh*(u2 - t2);
    float v3 = t3 + fh*(u3 - t3);

    float2 st = d_STAT[co];
    float4 m = *(const float4*)&mainf[(size_t)idx4*4];
    float4 r;
    r.x = fmaf(st.x, v0, st.y) + m.x;
    r.y = fmaf(st.x, v1, st.y) + m.y;
    r.z = fmaf(st.x, v2, st.y) + m.z;
    r.w = fmaf(st.x, v3, st.y) + m.w;
    *(float4*)&out[(size_t)idx4*4] = r;
}

// ---------------- launch ---------------------------------------------------
extern "C" void kernel_launch(void* const* d_in, const int* in_sizes, int n_in,
                              void* d_out, int out_size) {
    const float* mainf = (const float*)d_in[0];
    const float* crossf= (const float*)d_in[1];
    const float* gw    = (const float*)d_in[2];
    const float* gb    = (const float*)d_in[3];
    const float* tw    = (const float*)d_in[4];
    const float* tb    = (const float*)d_in[5];
    const float* pw    = (const float*)d_in[6];
    const float* pb    = (const float*)d_in[7];
    const float* ww    = (const float*)d_in[8];
    const float* wb    = (const float*)d_in[9];
    const float* bng   = (const float*)d_in[10];
    const float* bnb   = (const float*)d_in[11];
    float* out = (float*)d_out;

    qkv_kernel<<<dim3(32, BB), dim3(128, 2)>>>(crossf, mainf, gw, gb, tw, tb, pw, pb);
    attn_kernel<<<dim3(32, BB, KS), 128>>>();
    cw_kernel<<<128, 128>>>(ww, wb);
    bnpart_kernel<<<dim3(CC, 2), 256>>>();
    bnfin_kernel<<<1, 64>>>(bng, bnb);
    out_kernel<<<(BB*CC*HM*HM)/1024, 256>>>(mainf, out);
}